// round 2
// baseline (speedup 1.0000x reference)
#include <cuda_runtime.h>
#include <cuda_bf16.h>

// Problem constants (from reference): N=25000, K=32, F_IN=F_OUT=256
#define F 256
#define KNEIGH 32
#define N_MAX 25000

// Scratch: z[j] = relu(x[j] @ W + b), fp32. 25.6 MB device global (no runtime alloc).
__device__ float g_z[(size_t)N_MAX * F];

// ---------------------------------------------------------------------------
// Phase 1: z = relu(x @ W + b)   [M x 256] = [M x 256] @ [256 x 256]
// Classic tiled SGEMM: BM=128, BN=128, BK=16, 256 threads, 8x8 microtile.
// ---------------------------------------------------------------------------
#define BM 128
#define BN 128
#define BK 16
#define TM 8
#define TN 8

__global__ __launch_bounds__(256, 2)
void gemm_relu_kernel(const float* __restrict__ A,     // x  [M, F]
                      const float* __restrict__ W,     // W  [F, F]
                      const float* __restrict__ bias,  // b  [F]
                      int M)
{
    __shared__ float As[BK][BM];   // transposed A tile
    __shared__ float Bs[BK][BN];

    const int tid = threadIdx.x;
    const int rowBase = blockIdx.y * BM;
    const int colBase = blockIdx.x * BN;

    const int tRow = (tid / (BN / TN)) * TM;   // (tid/16)*8
    const int tCol = (tid % (BN / TN)) * TN;   // (tid%16)*8

    float acc[TM][TN];
    #pragma unroll
    for (int i = 0; i < TM; i++)
        #pragma unroll
        for (int j = 0; j < TN; j++)
            acc[i][j] = 0.0f;

    for (int kb = 0; kb < F; kb += BK) {
        // Load A tile: 128x16 = 512 float4, 2 per thread. Store transposed.
        #pragma unroll
        for (int p = 0; p < 2; p++) {
            int i = tid + p * 256;          // 0..511
            int r = i >> 2;                 // row within tile (0..127)
            int c4 = i & 3;                 // which float4 in the 16-float row
            int gRow = rowBase + r;
            float4 v;
            if (gRow < M) {
                v = *reinterpret_cast<const float4*>(&A[(size_t)gRow * F + kb + c4 * 4]);
            } else {
                v = make_float4(0.f, 0.f, 0.f, 0.f);
            }
            As[c4 * 4 + 0][r] = v.x;
            As[c4 * 4 + 1][r] = v.y;
            As[c4 * 4 + 2][r] = v.z;
            As[c4 * 4 + 3][r] = v.w;
        }
        // Load B tile (W): 16x128 = 512 float4, 2 per thread.
        #pragma unroll
        for (int p = 0; p < 2; p++) {
            int i = tid + p * 256;          // 0..511
            int r = i >> 5;                 // row 0..15
            int c4 = i & 31;                // which float4 in the 128-float row
            float4 v = *reinterpret_cast<const float4*>(&W[(size_t)(kb + r) * F + colBase + c4 * 4]);
            reinterpret_cast<float4*>(&Bs[r][0])[c4] = v;
        }
        __syncthreads();

        #pragma unroll
        for (int k = 0; k < BK; k++) {
            float ra[TM], rb[TN];
            float4 a0 = *reinterpret_cast<const float4*>(&As[k][tRow]);
            float4 a1 = *reinterpret_cast<const float4*>(&As[k][tRow + 4]);
            ra[0] = a0.x; ra[1] = a0.y; ra[2] = a0.z; ra[3] = a0.w;
            ra[4] = a1.x; ra[5] = a1.y; ra[6] = a1.z; ra[7] = a1.w;
            float4 b0 = *reinterpret_cast<const float4*>(&Bs[k][tCol]);
            float4 b1 = *reinterpret_cast<const float4*>(&Bs[k][tCol + 4]);
            rb[0] = b0.x; rb[1] = b0.y; rb[2] = b0.z; rb[3] = b0.w;
            rb[4] = b1.x; rb[5] = b1.y; rb[6] = b1.z; rb[7] = b1.w;
            #pragma unroll
            for (int i = 0; i < TM; i++)
                #pragma unroll
                for (int j = 0; j < TN; j++)
                    acc[i][j] = fmaf(ra[i], rb[j], acc[i][j]);
        }
        __syncthreads();
    }

    // Epilogue: add bias, ReLU, store (row-guarded).
    float bj[TN];
    #pragma unroll
    for (int j = 0; j < TN; j++) bj[j] = bias[colBase + tCol + j];

    #pragma unroll
    for (int i = 0; i < TM; i++) {
        int gRow = rowBase + tRow + i;
        if (gRow < M) {
            float4 o0, o1;
            o0.x = fmaxf(acc[i][0] + bj[0], 0.f);
            o0.y = fmaxf(acc[i][1] + bj[1], 0.f);
            o0.z = fmaxf(acc[i][2] + bj[2], 0.f);
            o0.w = fmaxf(acc[i][3] + bj[3], 0.f);
            o1.x = fmaxf(acc[i][4] + bj[4], 0.f);
            o1.y = fmaxf(acc[i][5] + bj[5], 0.f);
            o1.z = fmaxf(acc[i][6] + bj[6], 0.f);
            o1.w = fmaxf(acc[i][7] + bj[7], 0.f);
            float4* cp = reinterpret_cast<float4*>(&g_z[(size_t)gRow * F + colBase + tCol]);
            cp[0] = o0;
            cp[1] = o1;
        }
    }
}

// ---------------------------------------------------------------------------
// Phase 2: out[n] = max_k z[neigh[n,k]]
// 256 threads/block = 4 nodes x 64 threads; each thread owns one float4 column.
// neigh is int32 (JAX default x64-disabled aliases int64 -> int32).
// Indices clamped to [0, N) so a wrong dtype guess degrades to rel_err, not a crash.
// ---------------------------------------------------------------------------
#define NODES_PER_BLOCK 4

__global__ __launch_bounds__(256)
void pool_max_kernel(const int* __restrict__ neigh,   // [N, 32] int32
                     float* __restrict__ out,         // [N, 256]
                     int N)
{
    __shared__ int sidx[NODES_PER_BLOCK][KNEIGH];

    const int group = threadIdx.x >> 6;       // 0..3
    const int lane  = threadIdx.x & 63;       // 0..63 -> float4 column
    const int n = blockIdx.x * NODES_PER_BLOCK + group;

    // Cooperatively load the 4 nodes' neighbor lists (128 int32).
    if (threadIdx.x < NODES_PER_BLOCK * KNEIGH) {
        int g  = threadIdx.x >> 5;             // 0..3
        int kk = threadIdx.x & 31;             // 0..31
        int nn = blockIdx.x * NODES_PER_BLOCK + g;
        int v = (nn < N) ? neigh[(size_t)nn * KNEIGH + kk] : 0;
        // clamp for safety
        v = v < 0 ? 0 : (v >= N ? N - 1 : v);
        sidx[g][kk] = v;
    }
    __syncthreads();

    if (n >= N) return;

    int j0 = sidx[group][0];
    float4 m = reinterpret_cast<const float4*>(&g_z[(size_t)j0 * F])[lane];

    #pragma unroll
    for (int k = 1; k < KNEIGH; k++) {
        int j = sidx[group][k];
        float4 v = __ldg(&reinterpret_cast<const float4*>(&g_z[(size_t)j * F])[lane]);
        m.x = fmaxf(m.x, v.x);
        m.y = fmaxf(m.y, v.y);
        m.z = fmaxf(m.z, v.z);
        m.w = fmaxf(m.w, v.w);
    }

    reinterpret_cast<float4*>(&out[(size_t)n * F])[lane] = m;
}

// ---------------------------------------------------------------------------
// Launch: inputs per metadata order: x (f32), neigh (i32), W (f32), b (f32)
// ---------------------------------------------------------------------------
extern "C" void kernel_launch(void* const* d_in, const int* in_sizes, int n_in,
                              void* d_out, int out_size)
{
    const float* x     = (const float*)d_in[0];
    const int*   neigh = (const int*)d_in[1];
    const float* W     = (const float*)d_in[2];
    const float* bias  = (const float*)d_in[3];
    float*       out   = (float*)d_out;

    const int N = in_sizes[0] / F;   // 25000

    // Phase 1: z = relu(x @ W + b)
    dim3 gemmGrid(F / BN, (N + BM - 1) / BM);   // (2, 196)
    gemm_relu_kernel<<<gemmGrid, 256>>>(x, W, bias, N);

    // Phase 2: out[n] = max_k z[neigh[n,k]]
    int poolBlocks = (N + NODES_PER_BLOCK - 1) / NODES_PER_BLOCK;
    pool_max_kernel<<<poolBlocks, 256>>>(neigh, out, N);
}

// round 3
// speedup vs baseline: 1.8529x; 1.8529x over previous
#include <cuda_runtime.h>
#include <cuda_bf16.h>
#include <cstdint>

// Problem constants: N=25000, K=32, F_IN=F_OUT=256
#define F 256
#define KNEIGH 32
#define N_MAX 25000

// Scratch: z[j] = relu(x[j] @ W + b), fp32. 25.6 MB device global.
__device__ float g_z[(size_t)N_MAX * F];

// ---------------------------------------------------------------------------
// Phase 1: z = relu(x @ W + b) via tf32 tensor-core mma (m16n8k8).
// BM=128, BN=128, BK=32; 256 threads = 8 warps; warp tile 32x64.
// ---------------------------------------------------------------------------
#define BM 128
#define BN 128
#define BK 32

#define A_PITCH 36    // floats; bank = (4g + c) -> conflict-free frag loads
#define B_PITCH 136   // floats; bank = (8c + g) -> conflict-free frag loads

__device__ __forceinline__ uint32_t f2tf32(float f) {
    uint32_t u;
    asm("cvt.rna.tf32.f32 %0, %1;" : "=r"(u) : "f"(f));
    return u;
}

__device__ __forceinline__ void mma_tf32(float* d, const uint32_t* a,
                                         uint32_t b0, uint32_t b1) {
    asm volatile(
        "mma.sync.aligned.m16n8k8.row.col.f32.tf32.tf32.f32 "
        "{%0,%1,%2,%3}, {%4,%5,%6,%7}, {%8,%9}, {%0,%1,%2,%3};"
        : "+f"(d[0]), "+f"(d[1]), "+f"(d[2]), "+f"(d[3])
        : "r"(a[0]), "r"(a[1]), "r"(a[2]), "r"(a[3]), "r"(b0), "r"(b1));
}

__global__ __launch_bounds__(256, 2)
void gemm_relu_tf32(const float* __restrict__ A,     // x  [M, 256]
                    const float* __restrict__ W,     // W  [256, 256]
                    const float* __restrict__ bias,  // b  [256]
                    int M)
{
    __shared__ float As[BM * A_PITCH];   // 18432 B
    __shared__ float Bs[BK * B_PITCH];   // 17408 B

    const int tid  = threadIdx.x;
    const int lane = tid & 31;
    const int warp = tid >> 5;
    const int rowBase = blockIdx.y * BM;
    const int colBase = blockIdx.x * BN;

    const int warpM = (warp >> 1) * 32;  // 4 warp-rows
    const int warpN = (warp & 1) * 64;   // 2 warp-cols
    const int g = lane >> 2;             // 0..7
    const int c = lane & 3;              // 0..3

    float acc[2][8][4];
    #pragma unroll
    for (int i = 0; i < 2; i++)
        #pragma unroll
        for (int j = 0; j < 8; j++)
            #pragma unroll
            for (int q = 0; q < 4; q++)
                acc[i][j][q] = 0.0f;

    for (int kb = 0; kb < F; kb += BK) {
        // A tile: 128x32 floats = 1024 float4, 4/thread. Row-major, pitch 36.
        #pragma unroll
        for (int p = 0; p < 4; p++) {
            int i  = p * 256 + tid;          // 0..1023
            int r  = i >> 3;                 // 0..127
            int c4 = i & 7;                  // 0..7
            int gRow = rowBase + r;
            float4 v = make_float4(0.f, 0.f, 0.f, 0.f);
            if (gRow < M)
                v = *reinterpret_cast<const float4*>(&A[(size_t)gRow * F + kb + c4 * 4]);
            *reinterpret_cast<float4*>(&As[r * A_PITCH + c4 * 4]) = v;
        }
        // B tile: 32x128 floats = 1024 float4, 4/thread. Row-major, pitch 136.
        #pragma unroll
        for (int p = 0; p < 4; p++) {
            int i  = p * 256 + tid;          // 0..1023
            int r  = i >> 5;                 // 0..31
            int c4 = i & 31;                 // 0..31
            float4 v = *reinterpret_cast<const float4*>(
                &W[(size_t)(kb + r) * F + colBase + c4 * 4]);
            *reinterpret_cast<float4*>(&Bs[r * B_PITCH + c4 * 4]) = v;
        }
        __syncthreads();

        #pragma unroll
        for (int ks = 0; ks < BK; ks += 8) {
            // A fragments for the 2 m-tiles
            uint32_t aF[2][4];
            #pragma unroll
            for (int tm = 0; tm < 2; tm++) {
                int r0 = warpM + tm * 16 + g;
                aF[tm][0] = f2tf32(As[(r0    ) * A_PITCH + ks + c    ]);
                aF[tm][1] = f2tf32(As[(r0 + 8) * A_PITCH + ks + c    ]);
                aF[tm][2] = f2tf32(As[(r0    ) * A_PITCH + ks + c + 4]);
                aF[tm][3] = f2tf32(As[(r0 + 8) * A_PITCH + ks + c + 4]);
            }
            // B fragments + mma for the 8 n-tiles
            #pragma unroll
            for (int tn = 0; tn < 8; tn++) {
                int colS = warpN + tn * 8 + g;
                uint32_t b0 = f2tf32(Bs[(ks + c    ) * B_PITCH + colS]);
                uint32_t b1 = f2tf32(Bs[(ks + c + 4) * B_PITCH + colS]);
                mma_tf32(acc[0][tn], aF[0], b0, b1);
                mma_tf32(acc[1][tn], aF[1], b0, b1);
            }
        }
        __syncthreads();
    }

    // Epilogue: bias + ReLU, write z. Each lane owns 2-col pairs.
    #pragma unroll
    for (int tn = 0; tn < 8; tn++) {
        int col = colBase + warpN + tn * 8 + c * 2;
        float b0v = bias[col];
        float b1v = bias[col + 1];
        #pragma unroll
        for (int tm = 0; tm < 2; tm++) {
            int row0 = rowBase + warpM + tm * 16 + g;
            if (row0 < M) {
                float2 o;
                o.x = fmaxf(acc[tm][tn][0] + b0v, 0.f);
                o.y = fmaxf(acc[tm][tn][1] + b1v, 0.f);
                *reinterpret_cast<float2*>(&g_z[(size_t)row0 * F + col]) = o;
            }
            int row1 = row0 + 8;
            if (row1 < M) {
                float2 o;
                o.x = fmaxf(acc[tm][tn][2] + b0v, 0.f);
                o.y = fmaxf(acc[tm][tn][3] + b1v, 0.f);
                *reinterpret_cast<float2*>(&g_z[(size_t)row1 * F + col]) = o;
            }
        }
    }
}

// ---------------------------------------------------------------------------
// Phase 2: out[n] = max_k z[neigh[n,k]]  (unchanged; L2-gather bound)
// ---------------------------------------------------------------------------
#define NODES_PER_BLOCK 4

__global__ __launch_bounds__(256)
void pool_max_kernel(const int* __restrict__ neigh,   // [N, 32] int32
                     float* __restrict__ out,         // [N, 256]
                     int N)
{
    __shared__ int sidx[NODES_PER_BLOCK][KNEIGH];

    const int group = threadIdx.x >> 6;
    const int lane  = threadIdx.x & 63;
    const int n = blockIdx.x * NODES_PER_BLOCK + group;

    if (threadIdx.x < NODES_PER_BLOCK * KNEIGH) {
        int gg = threadIdx.x >> 5;
        int kk = threadIdx.x & 31;
        int nn = blockIdx.x * NODES_PER_BLOCK + gg;
        int v = (nn < N) ? neigh[(size_t)nn * KNEIGH + kk] : 0;
        v = v < 0 ? 0 : (v >= N ? N - 1 : v);
        sidx[gg][kk] = v;
    }
    __syncthreads();

    if (n >= N) return;

    int j0 = sidx[group][0];
    float4 m = reinterpret_cast<const float4*>(&g_z[(size_t)j0 * F])[lane];

    #pragma unroll
    for (int k = 1; k < KNEIGH; k++) {
        int j = sidx[group][k];
        float4 v = __ldg(&reinterpret_cast<const float4*>(&g_z[(size_t)j * F])[lane]);
        m.x = fmaxf(m.x, v.x);
        m.y = fmaxf(m.y, v.y);
        m.z = fmaxf(m.z, v.z);
        m.w = fmaxf(m.w, v.w);
    }

    reinterpret_cast<float4*>(&out[(size_t)n * F])[lane] = m;
}

// ---------------------------------------------------------------------------
// Launch: inputs: x (f32), neigh (i32), W (f32), b (f32)
// ---------------------------------------------------------------------------
extern "C" void kernel_launch(void* const* d_in, const int* in_sizes, int n_in,
                              void* d_out, int out_size)
{
    const float* x     = (const float*)d_in[0];
    const int*   neigh = (const int*)d_in[1];
    const float* W     = (const float*)d_in[2];
    const float* bias  = (const float*)d_in[3];
    float*       out   = (float*)d_out;

    const int N = in_sizes[0] / F;   // 25000

    dim3 gemmGrid(F / BN, (N + BM - 1) / BM);   // (2, 196)
    gemm_relu_tf32<<<gemmGrid, 256>>>(x, W, bias, N);

    int poolBlocks = (N + NODES_PER_BLOCK - 1) / NODES_PER_BLOCK;
    pool_max_kernel<<<poolBlocks, 256>>>(neigh, out, N);
}

// round 4
// speedup vs baseline: 2.5457x; 1.3739x over previous
#include <cuda_runtime.h>
#include <cuda_fp16.h>
#include <cuda_bf16.h>
#include <cstdint>

// Problem constants: N=25000, K=32, F_IN=F_OUT=256
#define F 256
#define KNEIGH 32
#define N_MAX 25000

// Scratch: z[j] = relu(x[j] @ W + b), stored fp16 (halves gather traffic). 12.8 MB.
__device__ __half g_z16[(size_t)N_MAX * F];

// ---------------------------------------------------------------------------
// Phase 1: z = relu(x @ W + b) via tf32 tensor-core mma (m16n8k8).
// BM=128, BN=128, BK=32; 256 threads = 8 warps; warp tile 32x64.
// ---------------------------------------------------------------------------
#define BM 128
#define BN 128
#define BK 32

#define A_PITCH 36    // floats; conflict-free fragment loads
#define B_PITCH 136

__device__ __forceinline__ uint32_t f2tf32(float f) {
    uint32_t u;
    asm("cvt.rna.tf32.f32 %0, %1;" : "=r"(u) : "f"(f));
    return u;
}

__device__ __forceinline__ void mma_tf32(float* d, const uint32_t* a,
                                         uint32_t b0, uint32_t b1) {
    asm volatile(
        "mma.sync.aligned.m16n8k8.row.col.f32.tf32.tf32.f32 "
        "{%0,%1,%2,%3}, {%4,%5,%6,%7}, {%8,%9}, {%0,%1,%2,%3};"
        : "+f"(d[0]), "+f"(d[1]), "+f"(d[2]), "+f"(d[3])
        : "r"(a[0]), "r"(a[1]), "r"(a[2]), "r"(a[3]), "r"(b0), "r"(b1));
}

__global__ __launch_bounds__(256, 2)
void gemm_relu_tf32(const float* __restrict__ A,     // x  [M, 256]
                    const float* __restrict__ W,     // W  [256, 256]
                    const float* __restrict__ bias,  // b  [256]
                    int M)
{
    __shared__ float As[BM * A_PITCH];
    __shared__ float Bs[BK * B_PITCH];

    const int tid  = threadIdx.x;
    const int lane = tid & 31;
    const int warp = tid >> 5;
    const int rowBase = blockIdx.y * BM;
    const int colBase = blockIdx.x * BN;

    const int warpM = (warp >> 1) * 32;
    const int warpN = (warp & 1) * 64;
    const int g = lane >> 2;             // 0..7
    const int c = lane & 3;              // 0..3

    float acc[2][8][4];
    #pragma unroll
    for (int i = 0; i < 2; i++)
        #pragma unroll
        for (int j = 0; j < 8; j++)
            #pragma unroll
            for (int q = 0; q < 4; q++)
                acc[i][j][q] = 0.0f;

    for (int kb = 0; kb < F; kb += BK) {
        #pragma unroll
        for (int p = 0; p < 4; p++) {
            int i  = p * 256 + tid;
            int r  = i >> 3;
            int c4 = i & 7;
            int gRow = rowBase + r;
            float4 v = make_float4(0.f, 0.f, 0.f, 0.f);
            if (gRow < M)
                v = *reinterpret_cast<const float4*>(&A[(size_t)gRow * F + kb + c4 * 4]);
            *reinterpret_cast<float4*>(&As[r * A_PITCH + c4 * 4]) = v;
        }
        #pragma unroll
        for (int p = 0; p < 4; p++) {
            int i  = p * 256 + tid;
            int r  = i >> 5;
            int c4 = i & 31;
            float4 v = *reinterpret_cast<const float4*>(
                &W[(size_t)(kb + r) * F + colBase + c4 * 4]);
            *reinterpret_cast<float4*>(&Bs[r * B_PITCH + c4 * 4]) = v;
        }
        __syncthreads();

        #pragma unroll
        for (int ks = 0; ks < BK; ks += 8) {
            uint32_t aF[2][4];
            #pragma unroll
            for (int tm = 0; tm < 2; tm++) {
                int r0 = warpM + tm * 16 + g;
                aF[tm][0] = f2tf32(As[(r0    ) * A_PITCH + ks + c    ]);
                aF[tm][1] = f2tf32(As[(r0 + 8) * A_PITCH + ks + c    ]);
                aF[tm][2] = f2tf32(As[(r0    ) * A_PITCH + ks + c + 4]);
                aF[tm][3] = f2tf32(As[(r0 + 8) * A_PITCH + ks + c + 4]);
            }
            #pragma unroll
            for (int tn = 0; tn < 8; tn++) {
                int colS = warpN + tn * 8 + g;
                uint32_t b0 = f2tf32(Bs[(ks + c    ) * B_PITCH + colS]);
                uint32_t b1 = f2tf32(Bs[(ks + c + 4) * B_PITCH + colS]);
                mma_tf32(acc[0][tn], aF[0], b0, b1);
                mma_tf32(acc[1][tn], aF[1], b0, b1);
            }
        }
        __syncthreads();
    }

    // Epilogue: bias + ReLU, convert to fp16, write z16.
    #pragma unroll
    for (int tn = 0; tn < 8; tn++) {
        int col = colBase + warpN + tn * 8 + c * 2;
        float b0v = bias[col];
        float b1v = bias[col + 1];
        #pragma unroll
        for (int tm = 0; tm < 2; tm++) {
            int row0 = rowBase + warpM + tm * 16 + g;
            if (row0 < M) {
                __half2 h = __floats2half2_rn(fmaxf(acc[tm][tn][0] + b0v, 0.f),
                                              fmaxf(acc[tm][tn][1] + b1v, 0.f));
                *reinterpret_cast<__half2*>(&g_z16[(size_t)row0 * F + col]) = h;
            }
            int row1 = row0 + 8;
            if (row1 < M) {
                __half2 h = __floats2half2_rn(fmaxf(acc[tm][tn][2] + b0v, 0.f),
                                              fmaxf(acc[tm][tn][3] + b1v, 0.f));
                *reinterpret_cast<__half2*>(&g_z16[(size_t)row1 * F + col]) = h;
            }
        }
    }
}

// ---------------------------------------------------------------------------
// Phase 2: out[n] = max_k z16[neigh[n,k]], fp16 compare (exact for max),
// convert winners to fp32. One warp per node: 32 lanes x 16B = 512B row.
// Indices in registers, broadcast by shuffle. No smem, no block sync.
// ---------------------------------------------------------------------------
__global__ __launch_bounds__(256)
void pool_max_kernel(const int* __restrict__ neigh,   // [N, 32] int32
                     float* __restrict__ out,         // [N, 256] fp32
                     int N)
{
    const int warp = threadIdx.x >> 5;            // 0..7 -> node within block
    const int lane = threadIdx.x & 31;
    const int n = blockIdx.x * 8 + warp;
    if (n >= N) return;

    // Each lane holds one neighbor index (coalesced 128B load).
    int jmine = neigh[(size_t)n * KNEIGH + lane];
    jmine = jmine < 0 ? 0 : (jmine >= N ? N - 1 : jmine);

    // k = 0 initializes the running max.
    int j0 = __shfl_sync(0xffffffffu, jmine, 0);
    uint4 v = reinterpret_cast<const uint4*>(&g_z16[(size_t)j0 * F])[lane];
    __half2 m0 = *reinterpret_cast<__half2*>(&v.x);
    __half2 m1 = *reinterpret_cast<__half2*>(&v.y);
    __half2 m2 = *reinterpret_cast<__half2*>(&v.z);
    __half2 m3 = *reinterpret_cast<__half2*>(&v.w);

    #pragma unroll
    for (int k = 1; k < KNEIGH; k++) {
        int j = __shfl_sync(0xffffffffu, jmine, k);
        uint4 u = __ldg(&reinterpret_cast<const uint4*>(&g_z16[(size_t)j * F])[lane]);
        m0 = __hmax2(m0, *reinterpret_cast<__half2*>(&u.x));
        m1 = __hmax2(m1, *reinterpret_cast<__half2*>(&u.y));
        m2 = __hmax2(m2, *reinterpret_cast<__half2*>(&u.z));
        m3 = __hmax2(m3, *reinterpret_cast<__half2*>(&u.w));
    }

    // Convert 8 fp16 -> 8 fp32 and store (two float4 = 32B per lane).
    float4 o0, o1;
    o0.x = __low2float(m0);  o0.y = __high2float(m0);
    o0.z = __low2float(m1);  o0.w = __high2float(m1);
    o1.x = __low2float(m2);  o1.y = __high2float(m2);
    o1.z = __low2float(m3);  o1.w = __high2float(m3);

    float4* op = reinterpret_cast<float4*>(&out[(size_t)n * F + lane * 8]);
    op[0] = o0;
    op[1] = o1;
}

// ---------------------------------------------------------------------------
// Launch: inputs: x (f32), neigh (i32), W (f32), b (f32)
// ---------------------------------------------------------------------------
extern "C" void kernel_launch(void* const* d_in, const int* in_sizes, int n_in,
                              void* d_out, int out_size)
{
    const float* x     = (const float*)d_in[0];
    const int*   neigh = (const int*)d_in[1];
    const float* W     = (const float*)d_in[2];
    const float* bias  = (const float*)d_in[3];
    float*       out   = (float*)d_out;

    const int N = in_sizes[0] / F;   // 25000

    dim3 gemmGrid(F / BN, (N + BM - 1) / BM);   // (2, 196)
    gemm_relu_tf32<<<gemmGrid, 256>>>(x, W, bias, N);

    int poolBlocks = (N + 7) / 8;   // 3125
    pool_max_kernel<<<poolBlocks, 256>>>(neigh, out, N);
}

// round 5
// speedup vs baseline: 3.2784x; 1.2878x over previous
#include <cuda_runtime.h>
#include <cuda_fp16.h>
#include <cuda_bf16.h>
#include <cstdint>

// Problem constants: N=25000, K=32, F_IN=F_OUT=256
#define F 256
#define KNEIGH 32
#define N_MAX 25000

// Scratch: z[j] = relu(x[j] @ W + b), stored fp16. 12.8 MB.
__device__ __half g_z16[(size_t)N_MAX * F];

// ---------------------------------------------------------------------------
// Phase 1: z = relu(x @ W + b) via fp16 mma (m16n8k16, fp32 accum).
// BM=128, BN=128, BK=32; 256 threads = 8 warps; warp tile 32x64.
// fp32->fp16 conversion happens once at smem-store; fragments via ldmatrix.
// Double-buffered smem, register prefetch, one __syncthreads per k-tile.
// ---------------------------------------------------------------------------
#define BM 128
#define BN 128
#define BK 32

#define PA 40    // halves per A smem row (pad 8) -> conflict-free ldmatrix
#define PB 136   // halves per B smem row (pad 8) -> conflict-free ldmatrix

__device__ __forceinline__ uint32_t smem_u32(const void* p) {
    return (uint32_t)__cvta_generic_to_shared(p);
}

__device__ __forceinline__ void ldsm_x4(uint32_t* r, uint32_t addr) {
    asm volatile("ldmatrix.sync.aligned.m8n8.x4.shared.b16 {%0,%1,%2,%3}, [%4];"
                 : "=r"(r[0]), "=r"(r[1]), "=r"(r[2]), "=r"(r[3]) : "r"(addr));
}
__device__ __forceinline__ void ldsm_x4_t(uint32_t* r, uint32_t addr) {
    asm volatile("ldmatrix.sync.aligned.m8n8.x4.trans.shared.b16 {%0,%1,%2,%3}, [%4];"
                 : "=r"(r[0]), "=r"(r[1]), "=r"(r[2]), "=r"(r[3]) : "r"(addr));
}
__device__ __forceinline__ void mma_f16(float* d, const uint32_t* a,
                                        uint32_t b0, uint32_t b1) {
    asm volatile(
        "mma.sync.aligned.m16n8k16.row.col.f32.f16.f16.f32 "
        "{%0,%1,%2,%3}, {%4,%5,%6,%7}, {%8,%9}, {%0,%1,%2,%3};"
        : "+f"(d[0]), "+f"(d[1]), "+f"(d[2]), "+f"(d[3])
        : "r"(a[0]), "r"(a[1]), "r"(a[2]), "r"(a[3]), "r"(b0), "r"(b1));
}

__device__ __forceinline__ uint2 pack_half4(float4 v) {
    __half2 h0 = __floats2half2_rn(v.x, v.y);
    __half2 h1 = __floats2half2_rn(v.z, v.w);
    uint2 u;
    u.x = *reinterpret_cast<uint32_t*>(&h0);
    u.y = *reinterpret_cast<uint32_t*>(&h1);
    return u;
}

__global__ __launch_bounds__(256, 2)
void gemm_relu_f16(const float* __restrict__ A,     // x  [M, 256]
                   const float* __restrict__ W,     // W  [256, 256]
                   const float* __restrict__ bias,  // b  [256]
                   int M)
{
    __shared__ __half As[2][BM * PA];   // 2 x 10240 B
    __shared__ __half Bs[2][BK * PB];   // 2 x  8704 B

    const int tid  = threadIdx.x;
    const int lane = tid & 31;
    const int warp = tid >> 5;
    const int rowBase = blockIdx.y * BM;
    const int colBase = blockIdx.x * BN;

    const int warpM = (warp >> 1) * 32;   // 0,32,64,96
    const int warpN = (warp & 1) * 64;    // 0,64
    const int g = lane >> 2;              // 0..7
    const int c = lane & 3;               // 0..3

    // Per-thread tile-load coordinates (4 float4 each for A and B).
    int arr[4], ac4[4], br[4], bc4[4];
    #pragma unroll
    for (int p = 0; p < 4; p++) {
        int i = p * 256 + tid;
        arr[p] = i >> 3;  ac4[p] = i & 7;    // A: 128 rows x 8 float4
        br[p]  = i >> 5;  bc4[p] = i & 31;   // B:  32 rows x 32 float4
    }

    float acc[2][8][4];
    #pragma unroll
    for (int i = 0; i < 2; i++)
        #pragma unroll
        for (int j = 0; j < 8; j++)
            #pragma unroll
            for (int q = 0; q < 4; q++)
                acc[i][j][q] = 0.0f;

    float4 va[4], vb[4];

    // Prologue: load k-tile 0 into regs, store to buffer 0.
    #pragma unroll
    for (int p = 0; p < 4; p++) {
        int gRow = rowBase + arr[p];
        va[p] = make_float4(0.f, 0.f, 0.f, 0.f);
        if (gRow < M)
            va[p] = *reinterpret_cast<const float4*>(&A[(size_t)gRow * F + ac4[p] * 4]);
        vb[p] = *reinterpret_cast<const float4*>(&W[(size_t)br[p] * F + colBase + bc4[p] * 4]);
    }
    #pragma unroll
    for (int p = 0; p < 4; p++) {
        *reinterpret_cast<uint2*>(&As[0][arr[p] * PA + ac4[p] * 4]) = pack_half4(va[p]);
        *reinterpret_cast<uint2*>(&Bs[0][br[p] * PB + bc4[p] * 4]) = pack_half4(vb[p]);
    }
    __syncthreads();

    // ldmatrix base addresses depend on lane only (per-buffer).
    const int lmod = lane & 15;
    const int ldiv = lane >> 4;

    #pragma unroll
    for (int kb = 0; kb < F / BK; kb++) {
        const int cur = kb & 1;
        const bool hasNext = (kb < F / BK - 1);

        // Prefetch next k-tile from gmem into registers (latency hidden by mma).
        if (hasNext) {
            int kOff = (kb + 1) * BK;
            #pragma unroll
            for (int p = 0; p < 4; p++) {
                int gRow = rowBase + arr[p];
                va[p] = make_float4(0.f, 0.f, 0.f, 0.f);
                if (gRow < M)
                    va[p] = *reinterpret_cast<const float4*>(
                        &A[(size_t)gRow * F + kOff + ac4[p] * 4]);
                vb[p] = *reinterpret_cast<const float4*>(
                    &W[(size_t)(kOff + br[p]) * F + colBase + bc4[p] * 4]);
            }
        }

        // Compute: two k16 steps.
        #pragma unroll
        for (int ks = 0; ks < 2; ks++) {
            uint32_t aF[2][4];
            #pragma unroll
            for (int tm = 0; tm < 2; tm++) {
                uint32_t addr = smem_u32(
                    &As[cur][(warpM + tm * 16 + lmod) * PA + ks * 16 + ldiv * 8]);
                ldsm_x4(aF[tm], addr);
            }
            #pragma unroll
            for (int tn2 = 0; tn2 < 4; tn2++) {
                uint32_t bF[4];
                uint32_t addr = smem_u32(
                    &Bs[cur][(ks * 16 + lmod) * PB + warpN + tn2 * 16 + ldiv * 8]);
                ldsm_x4_t(bF, addr);
                mma_f16(acc[0][tn2 * 2],     aF[0], bF[0], bF[1]);
                mma_f16(acc[1][tn2 * 2],     aF[1], bF[0], bF[1]);
                mma_f16(acc[0][tn2 * 2 + 1], aF[0], bF[2], bF[3]);
                mma_f16(acc[1][tn2 * 2 + 1], aF[1], bF[2], bF[3]);
            }
        }

        // Store prefetched tile into the other buffer.
        if (hasNext) {
            #pragma unroll
            for (int p = 0; p < 4; p++) {
                *reinterpret_cast<uint2*>(&As[cur ^ 1][arr[p] * PA + ac4[p] * 4]) = pack_half4(va[p]);
                *reinterpret_cast<uint2*>(&Bs[cur ^ 1][br[p] * PB + bc4[p] * 4]) = pack_half4(vb[p]);
            }
        }
        __syncthreads();
    }

    // Epilogue: bias + ReLU, convert to fp16, write z16.
    #pragma unroll
    for (int tn = 0; tn < 8; tn++) {
        int col = colBase + warpN + tn * 8 + c * 2;
        float b0v = bias[col];
        float b1v = bias[col + 1];
        #pragma unroll
        for (int tm = 0; tm < 2; tm++) {
            int row0 = rowBase + warpM + tm * 16 + g;
            if (row0 < M) {
                __half2 h = __floats2half2_rn(fmaxf(acc[tm][tn][0] + b0v, 0.f),
                                              fmaxf(acc[tm][tn][1] + b1v, 0.f));
                *reinterpret_cast<__half2*>(&g_z16[(size_t)row0 * F + col]) = h;
            }
            int row1 = row0 + 8;
            if (row1 < M) {
                __half2 h = __floats2half2_rn(fmaxf(acc[tm][tn][2] + b0v, 0.f),
                                              fmaxf(acc[tm][tn][3] + b1v, 0.f));
                *reinterpret_cast<__half2*>(&g_z16[(size_t)row1 * F + col]) = h;
            }
        }
    }
}

// ---------------------------------------------------------------------------
// Phase 2: out[n] = max_k z16[neigh[n,k]]; one warp per node, fp16 hmax2.
// ---------------------------------------------------------------------------
__global__ __launch_bounds__(256)
void pool_max_kernel(const int* __restrict__ neigh,   // [N, 32] int32
                     float* __restrict__ out,         // [N, 256] fp32
                     int N)
{
    const int warp = threadIdx.x >> 5;
    const int lane = threadIdx.x & 31;
    const int n = blockIdx.x * 8 + warp;
    if (n >= N) return;

    int jmine = neigh[(size_t)n * KNEIGH + lane];
    jmine = jmine < 0 ? 0 : (jmine >= N ? N - 1 : jmine);

    int j0 = __shfl_sync(0xffffffffu, jmine, 0);
    uint4 v = reinterpret_cast<const uint4*>(&g_z16[(size_t)j0 * F])[lane];
    __half2 m0 = *reinterpret_cast<__half2*>(&v.x);
    __half2 m1 = *reinterpret_cast<__half2*>(&v.y);
    __half2 m2 = *reinterpret_cast<__half2*>(&v.z);
    __half2 m3 = *reinterpret_cast<__half2*>(&v.w);

    #pragma unroll
    for (int k = 1; k < KNEIGH; k++) {
        int j = __shfl_sync(0xffffffffu, jmine, k);
        uint4 u = __ldg(&reinterpret_cast<const uint4*>(&g_z16[(size_t)j * F])[lane]);
        m0 = __hmax2(m0, *reinterpret_cast<__half2*>(&u.x));
        m1 = __hmax2(m1, *reinterpret_cast<__half2*>(&u.y));
        m2 = __hmax2(m2, *reinterpret_cast<__half2*>(&u.z));
        m3 = __hmax2(m3, *reinterpret_cast<__half2*>(&u.w));
    }

    float4 o0, o1;
    o0.x = __low2float(m0);  o0.y = __high2float(m0);
    o0.z = __low2float(m1);  o0.w = __high2float(m1);
    o1.x = __low2float(m2);  o1.y = __high2float(m2);
    o1.z = __low2float(m3);  o1.w = __high2float(m3);

    float4* op = reinterpret_cast<float4*>(&out[(size_t)n * F + lane * 8]);
    op[0] = o0;
    op[1] = o1;
}

// ---------------------------------------------------------------------------
// Launch: inputs: x (f32), neigh (i32), W (f32), b (f32)
// ---------------------------------------------------------------------------
extern "C" void kernel_launch(void* const* d_in, const int* in_sizes, int n_in,
                              void* d_out, int out_size)
{
    const float* x     = (const float*)d_in[0];
    const int*   neigh = (const int*)d_in[1];
    const float* W     = (const float*)d_in[2];
    const float* bias  = (const float*)d_in[3];
    float*       out   = (float*)d_out;

    const int N = in_sizes[0] / F;   // 25000

    dim3 gemmGrid(F / BN, (N + BM - 1) / BM);   // (2, 196)
    gemm_relu_f16<<<gemmGrid, 256>>>(x, W, bias, N);

    int poolBlocks = (N + 7) / 8;   // 3125
    pool_max_kernel<<<poolBlocks, 256>>>(neigh, out, N);
}

// round 6
// speedup vs baseline: 3.5584x; 1.0854x over previous
#include <cuda_runtime.h>
#include <cuda_fp16.h>
#include <cuda_bf16.h>
#include <cstdint>

// Problem constants: N=25000, K=32, F_IN=F_OUT=256
#define F 256
#define KNEIGH 32
#define N_MAX 25000

// Scratch: z fp16 (12.8 MB) + W fp16 (128 KB).
__device__ __half g_z16[(size_t)N_MAX * F];
__device__ __half g_w16[(size_t)F * F];

// ---------------------------------------------------------------------------
// Common helpers
// ---------------------------------------------------------------------------
__device__ __forceinline__ uint32_t smem_u32(const void* p) {
    return (uint32_t)__cvta_generic_to_shared(p);
}
__device__ __forceinline__ void ldsm_x4(uint32_t* r, uint32_t addr) {
    asm volatile("ldmatrix.sync.aligned.m8n8.x4.shared.b16 {%0,%1,%2,%3}, [%4];"
                 : "=r"(r[0]), "=r"(r[1]), "=r"(r[2]), "=r"(r[3]) : "r"(addr));
}
__device__ __forceinline__ void ldsm_x4_t(uint32_t* r, uint32_t addr) {
    asm volatile("ldmatrix.sync.aligned.m8n8.x4.trans.shared.b16 {%0,%1,%2,%3}, [%4];"
                 : "=r"(r[0]), "=r"(r[1]), "=r"(r[2]), "=r"(r[3]) : "r"(addr));
}
__device__ __forceinline__ void mma_f16(float* d, const uint32_t* a,
                                        uint32_t b0, uint32_t b1) {
    asm volatile(
        "mma.sync.aligned.m16n8k16.row.col.f32.f16.f16.f32 "
        "{%0,%1,%2,%3}, {%4,%5,%6,%7}, {%8,%9}, {%0,%1,%2,%3};"
        : "+f"(d[0]), "+f"(d[1]), "+f"(d[2]), "+f"(d[3])
        : "r"(a[0]), "r"(a[1]), "r"(a[2]), "r"(a[3]), "r"(b0), "r"(b1));
}
__device__ __forceinline__ uint2 pack_half4(float4 v) {
    __half2 h0 = __floats2half2_rn(v.x, v.y);
    __half2 h1 = __floats2half2_rn(v.z, v.w);
    uint2 u;
    u.x = *reinterpret_cast<uint32_t*>(&h0);
    u.y = *reinterpret_cast<uint32_t*>(&h1);
    return u;
}

// ---------------------------------------------------------------------------
// Kernel 0: convert W fp32 -> fp16 (once per launch; 64KB write, trivial)
// ---------------------------------------------------------------------------
__global__ void convert_w_kernel(const float* __restrict__ W) {
    int i = blockIdx.x * 256 + threadIdx.x;          // 16384 float4s
    float4 v = reinterpret_cast<const float4*>(W)[i];
    reinterpret_cast<uint2*>(g_w16)[i] = pack_half4(v);
}

// ---------------------------------------------------------------------------
// Phase 1: persistent-W GEMM. 148 blocks (1/SM), 256 threads = 8 warps.
// Full fp16 W (256x256, pitch 264) resident in smem; loop over 64-row x chunks
// with double-buffered A tiles. Warp tile 32x64 (m16n8k16 fp16, fp32 accum).
// ---------------------------------------------------------------------------
#define CHUNK 64
#define PW 264   // halves per W smem row (pad 8) -> conflict-free ldmatrix
#define PA 264   // halves per A smem row

#define SMEM_W_HALVES (F * PW)                 // 67584 halves = 135168 B
#define SMEM_A_HALVES (CHUNK * PA)             // 16896 halves =  33792 B
#define SMEM_TOTAL_BYTES ((SMEM_W_HALVES + 2 * SMEM_A_HALVES) * 2)  // 202752 B

__global__ __launch_bounds__(256, 1)
void gemm_relu_persist(const float* __restrict__ A,     // x [M, 256] fp32
                       const float* __restrict__ bias,  // [256] fp32
                       int M, int nChunks)
{
    extern __shared__ __align__(16) __half dyn[];
    __half* Ws = dyn;                                   // [256][PW]
    __half* As[2] = { dyn + SMEM_W_HALVES,
                      dyn + SMEM_W_HALVES + SMEM_A_HALVES };

    const int tid  = threadIdx.x;
    const int lane = tid & 31;
    const int warp = tid >> 5;

    const int warpM = (warp >> 2) * 32;    // {0, 32}
    const int warpN = (warp & 3) * 64;     // {0, 64, 128, 192}
    const int g = lane >> 2;               // 0..7
    const int c = lane & 3;                // 0..3
    const int lmod = lane & 15;
    const int ldiv = lane >> 4;

    // ---- Load full fp16 W into smem (32 x uint4 per thread) ----
    #pragma unroll 8
    for (int p = 0; p < 32; p++) {
        int i = p * 256 + tid;             // 0..8191, 16B chunks
        int r = i >> 5;                    // row 0..255
        int s = i & 31;                    // 16B segment within row
        uint4 v = reinterpret_cast<const uint4*>(g_w16)[i];
        *reinterpret_cast<uint4*>(&Ws[r * PW + s * 8]) = v;
    }

    int chunk = blockIdx.x;
    if (chunk >= nChunks) return;          // not possible at grid=148, chunks=391

    // ---- Initial A chunk into buffer 0 ----
    {
        float4 v[16];
        #pragma unroll
        for (int p = 0; p < 16; p++) {
            int i = p * 256 + tid;         // 0..4095 float4s (64 rows x 64 f4)
            int r = i >> 6;
            int c4 = i & 63;
            int row = chunk * CHUNK + r;
            v[p] = make_float4(0.f, 0.f, 0.f, 0.f);
            if (row < M)
                v[p] = *reinterpret_cast<const float4*>(&A[(size_t)row * F + c4 * 4]);
        }
        #pragma unroll
        for (int p = 0; p < 16; p++) {
            int i = p * 256 + tid;
            int r = i >> 6;
            int c4 = i & 63;
            *reinterpret_cast<uint2*>(&As[0][r * PA + c4 * 4]) = pack_half4(v[p]);
        }
    }
    __syncthreads();

    int cur = 0;
    while (true) {
        const int next = chunk + gridDim.x;
        const bool hasNext = next < nChunks;

        float acc[2][8][4];
        #pragma unroll
        for (int i = 0; i < 2; i++)
            #pragma unroll
            for (int j = 0; j < 8; j++)
                #pragma unroll
                for (int q = 0; q < 4; q++)
                    acc[i][j][q] = 0.0f;

        float4 va[8];

        #pragma unroll
        for (int h = 0; h < 2; h++) {
            // Prefetch half of next A chunk (rows h*32 .. h*32+31).
            if (hasNext) {
                #pragma unroll
                for (int p = 0; p < 8; p++) {
                    int i = (h * 8 + p) * 256 + tid;
                    int r = i >> 6;
                    int c4 = i & 63;
                    int row = next * CHUNK + r;
                    va[p] = make_float4(0.f, 0.f, 0.f, 0.f);
                    if (row < M)
                        va[p] = *reinterpret_cast<const float4*>(&A[(size_t)row * F + c4 * 4]);
                }
            }
            // Compute k16 steps h*8 .. h*8+7 from buffer cur (W resident).
            #pragma unroll
            for (int ks = 0; ks < 8; ks++) {
                int kk = h * 8 + ks;
                uint32_t aF[2][4];
                #pragma unroll
                for (int tm = 0; tm < 2; tm++) {
                    uint32_t addr = smem_u32(
                        &As[cur][(warpM + tm * 16 + lmod) * PA + kk * 16 + ldiv * 8]);
                    ldsm_x4(aF[tm], addr);
                }
                #pragma unroll
                for (int tn2 = 0; tn2 < 4; tn2++) {
                    uint32_t bF[4];
                    uint32_t addr = smem_u32(
                        &Ws[(kk * 16 + lmod) * PW + warpN + tn2 * 16 + ldiv * 8]);
                    ldsm_x4_t(bF, addr);
                    mma_f16(acc[0][tn2 * 2],     aF[0], bF[0], bF[1]);
                    mma_f16(acc[1][tn2 * 2],     aF[1], bF[0], bF[1]);
                    mma_f16(acc[0][tn2 * 2 + 1], aF[0], bF[2], bF[3]);
                    mma_f16(acc[1][tn2 * 2 + 1], aF[1], bF[2], bF[3]);
                }
            }
            // Store prefetched half into the other buffer.
            if (hasNext) {
                #pragma unroll
                for (int p = 0; p < 8; p++) {
                    int i = (h * 8 + p) * 256 + tid;
                    int r = i >> 6;
                    int c4 = i & 63;
                    *reinterpret_cast<uint2*>(&As[cur ^ 1][r * PA + c4 * 4]) = pack_half4(va[p]);
                }
            }
        }

        // Epilogue: bias + ReLU -> z16 for this chunk.
        #pragma unroll
        for (int tn = 0; tn < 8; tn++) {
            int col = warpN + tn * 8 + c * 2;
            float b0v = bias[col];
            float b1v = bias[col + 1];
            #pragma unroll
            for (int tm = 0; tm < 2; tm++) {
                int row0 = chunk * CHUNK + warpM + tm * 16 + g;
                if (row0 < M) {
                    __half2 hh = __floats2half2_rn(fmaxf(acc[tm][tn][0] + b0v, 0.f),
                                                   fmaxf(acc[tm][tn][1] + b1v, 0.f));
                    *reinterpret_cast<__half2*>(&g_z16[(size_t)row0 * F + col]) = hh;
                }
                int row1 = row0 + 8;
                if (row1 < M) {
                    __half2 hh = __floats2half2_rn(fmaxf(acc[tm][tn][2] + b0v, 0.f),
                                                   fmaxf(acc[tm][tn][3] + b1v, 0.f));
                    *reinterpret_cast<__half2*>(&g_z16[(size_t)row1 * F + col]) = hh;
                }
            }
        }

        if (!hasNext) break;
        __syncthreads();          // next buffer fully written before reading
        chunk = next;
        cur ^= 1;
    }
}

// ---------------------------------------------------------------------------
// Phase 2: out[n] = max_k z16[neigh[n,k]]; one warp per node, fp16 hmax2.
// ---------------------------------------------------------------------------
__global__ __launch_bounds__(256)
void pool_max_kernel(const int* __restrict__ neigh,   // [N, 32] int32
                     float* __restrict__ out,         // [N, 256] fp32
                     int N)
{
    const int warp = threadIdx.x >> 5;
    const int lane = threadIdx.x & 31;
    const int n = blockIdx.x * 8 + warp;
    if (n >= N) return;

    int jmine = neigh[(size_t)n * KNEIGH + lane];
    jmine = jmine < 0 ? 0 : (jmine >= N ? N - 1 : jmine);

    int j0 = __shfl_sync(0xffffffffu, jmine, 0);
    uint4 v = reinterpret_cast<const uint4*>(&g_z16[(size_t)j0 * F])[lane];
    __half2 m0 = *reinterpret_cast<__half2*>(&v.x);
    __half2 m1 = *reinterpret_cast<__half2*>(&v.y);
    __half2 m2 = *reinterpret_cast<__half2*>(&v.z);
    __half2 m3 = *reinterpret_cast<__half2*>(&v.w);

    #pragma unroll
    for (int k = 1; k < KNEIGH; k++) {
        int j = __shfl_sync(0xffffffffu, jmine, k);
        uint4 u = __ldg(&reinterpret_cast<const uint4*>(&g_z16[(size_t)j * F])[lane]);
        m0 = __hmax2(m0, *reinterpret_cast<__half2*>(&u.x));
        m1 = __hmax2(m1, *reinterpret_cast<__half2*>(&u.y));
        m2 = __hmax2(m2, *reinterpret_cast<__half2*>(&u.z));
        m3 = __hmax2(m3, *reinterpret_cast<__half2*>(&u.w));
    }

    float4 o0, o1;
    o0.x = __low2float(m0);  o0.y = __high2float(m0);
    o0.z = __low2float(m1);  o0.w = __high2float(m1);
    o1.x = __low2float(m2);  o1.y = __high2float(m2);
    o1.z = __low2float(m3);  o1.w = __high2float(m3);

    float4* op = reinterpret_cast<float4*>(&out[(size_t)n * F + lane * 8]);
    op[0] = o0;
    op[1] = o1;
}

// ---------------------------------------------------------------------------
// Launch: inputs: x (f32), neigh (i32), W (f32), b (f32)
// ---------------------------------------------------------------------------
extern "C" void kernel_launch(void* const* d_in, const int* in_sizes, int n_in,
                              void* d_out, int out_size)
{
    const float* x     = (const float*)d_in[0];
    const int*   neigh = (const int*)d_in[1];
    const float* W     = (const float*)d_in[2];
    const float* bias  = (const float*)d_in[3];
    float*       out   = (float*)d_out;

    const int N = in_sizes[0] / F;                 // 25000
    const int nChunks = (N + CHUNK - 1) / CHUNK;   // 391

    // Opt in to large dynamic smem (idempotent; host-side, not captured work).
    cudaFuncSetAttribute(gemm_relu_persist,
                         cudaFuncAttributeMaxDynamicSharedMemorySize,
                         SMEM_TOTAL_BYTES);

    convert_w_kernel<<<64, 256>>>(W);
    gemm_relu_persist<<<148, 256, SMEM_TOTAL_BYTES>>>(x, bias, N, nChunks);

    int poolBlocks = (N + 7) / 8;   // 3125
    pool_max_kernel<<<poolBlocks, 256>>>(neigh, out, N);
}